// round 2
// baseline (speedup 1.0000x reference)
#include <cuda_runtime.h>
#include <cuda_bf16.h>

// Problem constants
#define BB 4
#define HH 4
#define VV 8
#define NN 16384
#define FD 32
#define NC 32768   // 32*32*32

// ---------------------------------------------------------------------------
// Kernel 1: zero the output (harness poisons it with 0xAA).
// 16,777,216 floats = 4,194,304 float4.
// ---------------------------------------------------------------------------
__global__ void splat_zero_kernel(float4* __restrict__ out) {
    int i = blockIdx.x * blockDim.x + threadIdx.x;
    out[i] = make_float4(0.f, 0.f, 0.f, 0.f);
}

// ---------------------------------------------------------------------------
// Kernel 2: scatter-max splat.
// One thread per (b,h,n). gridDim.y = b*H+h (16), gridDim.x covers n.
//
// out[bh, f, c] = max(0, max_{v,n: idx[bh,v,n]==c} feat[bh,f,n]*lc[bh,v,n])
//
// lc >= 0 (uniform[0,1)), out init 0  =>  only feat > 0 contributes.
// Positive fp32 bit patterns are monotone as signed int => atomicMax on int.
// ---------------------------------------------------------------------------
__global__ void splat_kernel(const float* __restrict__ lc,
                             const int* __restrict__ fidx,
                             const float* __restrict__ feats,
                             int* __restrict__ out) {
    const int n  = blockIdx.x * blockDim.x + threadIdx.x;   // 0..NN-1
    const int bh = blockIdx.y;                               // 0..15

    // Load the 8 (index, coordinate) pairs for this (bh, n). Coalesced in n.
    int   idxs[VV];
    float lcs[VV];
#pragma unroll
    for (int v = 0; v < VV; v++) {
        const int base = (bh * VV + v) * NN + n;
        idxs[v] = fidx[base] & (NC - 1);   // mask: defensive bound
        lcs[v]  = lc[base];
    }

    // features layout: [B, H*FD, N] == [bh*FD + f][n]
    const float* fp = feats + (long long)bh * FD * NN + n;
    int* const  op  = out + (long long)bh * FD * NC;

#pragma unroll 4
    for (int f = 0; f < FD; f++) {
        const float fv = fp[(long long)f * NN];      // coalesced in n
        if (fv > 0.f) {
            int* const obase = op + f * NC;
#pragma unroll
            for (int v = 0; v < VV; v++) {
                const float val = fv * lcs[v];
                if (val > 0.f) {
                    atomicMax(obase + idxs[v], __float_as_int(val));
                }
            }
        }
    }
}

// ---------------------------------------------------------------------------
// kernel_launch
// inputs (metadata order):
//   d_in[0] local_coordinate  float32  [B,H,V,N]   = 2,097,152
//   d_in[1] flattened_index   int32    [B,H,V,N]   = 2,097,152
//   d_in[2] features          float32  [B,128,N]   = 8,388,608
// output: float32 [B, 128, 32,32,32] = 16,777,216
// ---------------------------------------------------------------------------
extern "C" void kernel_launch(void* const* d_in, const int* in_sizes, int n_in,
                              void* d_out, int out_size) {
    const float* lc    = (const float*)d_in[0];
    const int*   fidx  = (const int*)d_in[1];
    const float* feats = (const float*)d_in[2];
    float*       out   = (float*)d_out;

    // Zero the output: 16,777,216 floats -> 4,194,304 float4 -> 16384 blocks.
    {
        const int n4 = (BB * HH * FD * NC) / 4;
        splat_zero_kernel<<<n4 / 256, 256>>>((float4*)out);
    }

    // Scatter-max.
    {
        dim3 block(256, 1, 1);
        dim3 grid(NN / 256, BB * HH, 1);
        splat_kernel<<<grid, block>>>(lc, fidx, feats, (int*)out);
    }
}